// round 13
// baseline (speedup 1.0000x reference)
#include <cuda_runtime.h>
#include <math_constants.h>

#define BATCH   8
#define NSHAPE  8192
#define NSKEL   2048

#define NSLAB   128
#define XMIN    (-6.0f)
#define INVW    (NSLAB / 12.0f)        /* 10.6667: 128 slabs over [-6,6] */

#define SHCAP   1024                   /* >=3.3x expected peak slab count */
#define SKCAP   384                    /* >=5x expected peak slab count  */
#define SUBS1   8                      /* SHCAP/128 query sub-blocks */
#define SUBS2   3                      /* SKCAP/128 */
#define B1      (BATCH * NSLAB * SUBS1)    /* 8192 */
#define B2      (BATCH * NSLAB * SUBS2)    /* 3072 */
#define NBLK    (B1 + B2)                  /* 11264 */
#define TOTW    (NBLK * 4)

// Slab-bucketed clouds as float4 (x,y,z,|p|^2). Counts reset by the last
// finishing warp each call; accum/done self-reset => graph-replay safe,
// no allocations (all __device__ globals, zero-initialized at load).
__device__ float4   g_shp[BATCH][NSLAB * SHCAP];
__device__ float4   g_skp[BATCH][NSLAB * SKCAP];
__device__ unsigned g_cntSh[BATCH][NSLAB];
__device__ unsigned g_cntSk[BATCH][NSLAB];
__device__ float    g_accum;
__device__ unsigned g_done;

// ---------------------------------------------------------------------------
__device__ __forceinline__ int xbin(float x) {
    int s = (int)floorf((x - XMIN) * INVW);
    return min(max(s, 0), NSLAB - 1);
}
__device__ __forceinline__ float wminf(float v) {
#pragma unroll
    for (int o = 16; o > 0; o >>= 1) v = fminf(v, __shfl_xor_sync(0xffffffffu, v, o));
    return v;
}
__device__ __forceinline__ float wmaxf(float v) {
#pragma unroll
    for (int o = 16; o > 0; o >>= 1) v = fmaxf(v, __shfl_xor_sync(0xffffffffu, v, o));
    return v;
}
__device__ __forceinline__ float wsumf(float v) {
#pragma unroll
    for (int o = 16; o > 0; o >>= 1) v += __shfl_xor_sync(0xffffffffu, v, o);
    return v;
}

// scan n slab points (uniform LDG.128 broadcast); m = min over (|p|^2 - 2 q.p)
__device__ __forceinline__ void scan_slab(
    const float4* __restrict__ p, int n,
    float cx, float cy, float cz, float& m)
{
    int j = 0;
    for (; j + 4 <= n; j += 4) {
        const float4 a = __ldg(p + j + 0);
        const float4 b = __ldg(p + j + 1);
        const float4 c = __ldg(p + j + 2);
        const float4 d = __ldg(p + j + 3);
        float t0 = fmaf(cx, a.x, a.w); t0 = fmaf(cy, a.y, t0); t0 = fmaf(cz, a.z, t0);
        float t1 = fmaf(cx, b.x, b.w); t1 = fmaf(cy, b.y, t1); t1 = fmaf(cz, b.z, t1);
        float t2 = fmaf(cx, c.x, c.w); t2 = fmaf(cy, c.y, t2); t2 = fmaf(cz, c.z, t2);
        float t3 = fmaf(cx, d.x, d.w); t3 = fmaf(cy, d.y, t3); t3 = fmaf(cz, d.z, t3);
        m = fminf(m, fminf(fminf(t0, t1), fminf(t2, t3)));
    }
    for (; j < n; j++) {
        const float4 a = __ldg(p + j);
        float t = fmaf(cx, a.x, a.w); t = fmaf(cy, a.y, t); t = fmaf(cz, a.z, t);
        m = fminf(m, t);
    }
}

// ---------------------------------------------------------------------------
// Prep: bucket every point of both clouds into its x-slab via atomic slot.
// Order within a slab is irrelevant (exact min); counts start at zero
// (zero-init first run; reset by scan finalizer on every call).
// ---------------------------------------------------------------------------
__global__ void __launch_bounds__(256) prep_kernel(
    const float* __restrict__ shape, const float* __restrict__ skel)
{
    const int i = blockIdx.x * 256 + threadIdx.x;
    if (i < BATCH * NSHAPE) {
        const int b = i >> 13;
        const float* p = shape + (size_t)i * 6;
        const float x = p[0], y = p[1], z = p[2];
        const int s = xbin(x);
        const unsigned slot = atomicAdd(&g_cntSh[b][s], 1u);
        if (slot < SHCAP)
            g_shp[b][s * SHCAP + slot] =
                make_float4(x, y, z, fmaf(x, x, fmaf(y, y, z * z)));
    } else {
        const int j = i - BATCH * NSHAPE;
        if (j < BATCH * NSKEL) {
            const int b = j >> 11;
            const float* p = skel + (size_t)j * 3;
            const float x = p[0], y = p[1], z = p[2];
            const int s = xbin(x);
            const unsigned slot = atomicAdd(&g_cntSk[b][s], 1u);
            if (slot < SKCAP)
                g_skp[b][s * SKCAP + slot] =
                    make_float4(x, y, z, fmaf(x, x, fmaf(y, y, z * z)));
        }
    }
}

// ---------------------------------------------------------------------------
// Scan: block = (side, batch, query-slab, sub); warp = 32 queries of that
// slab (x-coherent). Per warp (all control lane-uniform, shfl only):
//   phase A: scan counterpart slab at warp x-mid (expand ring while empty)
//            -> exact upper bound per query
//   window:  warp-max radius -> exact slab range [qxmin-r, qxmax+r]
//   scan remaining slabs; d = sqrt(max(qn + min_t, 0)); warp-sum -> atomicAdd.
// Completion: every warp bumps g_done; the last warp writes out[0] and zeros
// the slab counters for the next graph replay.
// ---------------------------------------------------------------------------
__global__ void __launch_bounds__(128) scan_kernel(float* __restrict__ out)
{
    const int tid  = threadIdx.x;
    const int w    = tid >> 5;
    const int lane = tid & 31;
    const int bid  = blockIdx.x;

    int b, slab, qstart, CCAP;
    unsigned cntQ;
    const float4 *qp, *cp;
    const unsigned* ccnt;

    if (bid < B1) {                 // queries = shape slab, counterpart = skel
        b = bid / (NSLAB * SUBS1);
        const int r = bid % (NSLAB * SUBS1);
        slab = r / SUBS1;
        qstart = (r % SUBS1) * 128 + w * 32;
        cntQ = min(g_cntSh[b][slab], (unsigned)SHCAP);
        qp = g_shp[b] + slab * SHCAP;
        cp = g_skp[b]; ccnt = g_cntSk[b]; CCAP = SKCAP;
    } else {                        // queries = skel slab, counterpart = shape
        const int t = bid - B1;
        b = t / (NSLAB * SUBS2);
        const int r = t % (NSLAB * SUBS2);
        slab = r / SUBS2;
        qstart = (r % SUBS2) * 128 + w * 32;
        cntQ = min(g_cntSk[b][slab], (unsigned)SKCAP);
        qp = g_skp[b] + slab * SKCAP;
        cp = g_shp[b]; ccnt = g_cntSh[b]; CCAP = SHCAP;
    }

    if (qstart < (int)cntQ) {
        const int qidx = qstart + lane;
        const bool act = qidx < (int)cntQ;
        const float4 q = qp[min(qidx, (int)cntQ - 1)];
        const float cx = -2.0f * q.x, cy = -2.0f * q.y, cz = -2.0f * q.z;

        const float qxmin = wminf(q.x);
        const float qxmax = wmaxf(q.x);

        // ---- phase A: counterpart slab at warp x-mid, expand while empty ----
        float m = CUDART_INF_F;
        const int sc = xbin(0.5f * (qxmin + qxmax));
        int pa0 = sc, pa1 = sc;
        int np = min((int)ccnt[sc], CCAP);
        scan_slab(cp + sc * CCAP, np, cx, cy, cz, m);
        while (np == 0) {
            bool any = false;
            if (pa0 > 0) {
                pa0--;
                const int c = min((int)ccnt[pa0], CCAP);
                scan_slab(cp + pa0 * CCAP, c, cx, cy, cz, m);
                np += c; any = true;
            }
            if (pa1 < NSLAB - 1) {
                pa1++;
                const int c = min((int)ccnt[pa1], CCAP);
                scan_slab(cp + pa1 * CCAP, c, cx, cy, cz, m);
                np += c; any = true;
            }
            if (!any) break;
        }

        // ---- exact window from warp-max radius ----
        const float rad  = sqrtf(fmaxf(q.w + m, 0.0f)) * 1.0001f;
        const float rmax = wmaxf(rad);
        const int tLo = xbin(qxmin - rmax);
        const int tHi = xbin(qxmax + rmax);
        for (int t = tLo; t <= tHi; t++) {
            if (t >= pa0 && t <= pa1) continue;       // already scanned
            scan_slab(cp + t * CCAP, min((int)ccnt[t], CCAP), cx, cy, cz, m);
        }

        const float d  = sqrtf(fmaxf(q.w + m, 0.0f));
        const float ws = wsumf(act ? d : 0.0f);
        if (lane == 0) atomicAdd(&g_accum, ws);
    }

    // ---- per-warp completion ----
    __threadfence();
    unsigned old = 0;
    if (lane == 0) old = atomicAdd(&g_done, 1u);
    old = __shfl_sync(0xffffffffu, old, 0);
    if (old == TOTW - 1) {
        __threadfence();
        unsigned* c1 = &g_cntSh[0][0];
        unsigned* c2 = &g_cntSk[0][0];
        for (int i = lane; i < BATCH * NSLAB; i += 32) { c1[i] = 0; c2[i] = 0; }
        if (lane == 0) {
            out[0] = atomicExch(&g_accum, 0.0f) * 1.0e-4f;
            g_done = 0;
        }
    }
}

// ---------------------------------------------------------------------------
extern "C" void kernel_launch(void* const* d_in, const int* in_sizes, int n_in,
                              void* d_out, int out_size)
{
    const float* shape = (const float*)d_in[0];  // (8, 8192, 6) fp32
    const float* skel  = (const float*)d_in[1];  // (8, 2048, 3) fp32
    prep_kernel<<<(BATCH * NSHAPE + BATCH * NSKEL + 255) / 256, 256>>>(shape, skel);
    scan_kernel<<<NBLK, 128>>>((float*)d_out);
}

// round 16
// speedup vs baseline: 2.6450x; 2.6450x over previous
#include <cuda_runtime.h>
#include <math_constants.h>

#define BATCH   8
#define NSHAPE  8192
#define NSKEL   2048

#define NSLAB   64
#define XMIN    (-6.0f)
#define INVW    5.3333333f             /* 64 slabs over [-6,6] */

#define SHCAP   1024                   /* shape slab capacity (peak ~700) */
#define SKCAP   256                    /* skel slab capacity (peak ~200) */
#define QG      256                    /* queries per group */
#define SUB1    4                      /* SHCAP/QG */
#define NG1     (BATCH * NSLAB * SUB1) /* 2048 */
#define NG2     (BATCH * NSLAB)        /* 512 */
#define NG      (NG1 + NG2)            /* 2560 */
#define MAXCH   4                      /* chunk blocks per group */
#define SCANBLK (NG * MAXCH)           /* 10240 */

// Slab-bucketed clouds as float4 (x,y,z,|p|^2). All counters/keys either
// rewritten each call or self-resetting => graph-replay safe, no allocations.
// Key = ~bits(d2): monotone-decreasing map, so atomicMax == min(d2).
__device__ float4   g_shp[BATCH][NSLAB * SHCAP];
__device__ float4   g_skp[BATCH][NSLAB * SKCAP];
__device__ unsigned g_cntSh[BATCH][NSLAB];
__device__ unsigned g_cntSk[BATCH][NSLAB];
__device__ int      g_s0[NG], g_s1[NG];     // per-group slab window
__device__ unsigned g_key[NG * QG];         // seeded by bound each call
__device__ unsigned g_gc[NG];
__device__ unsigned g_done;
__device__ float    g_accum;

// ---------------------------------------------------------------------------
__device__ __forceinline__ int xbin(float x) {
    int s = (int)floorf((x - XMIN) * INVW);
    return min(max(s, 0), NSLAB - 1);
}

// dense scan of n smem points; m = min over (|p|^2 - 2 q.p)
__device__ __forceinline__ void scan_pts(
    const float4* __restrict__ t, int n,
    float cx, float cy, float cz, float& m)
{
    int j = 0;
    for (; j + 4 <= n; j += 4) {
        const float4 a = t[j + 0];
        const float4 b = t[j + 1];
        const float4 c = t[j + 2];
        const float4 d = t[j + 3];
        float t0 = fmaf(cx, a.x, a.w); t0 = fmaf(cy, a.y, t0); t0 = fmaf(cz, a.z, t0);
        float t1 = fmaf(cx, b.x, b.w); t1 = fmaf(cy, b.y, t1); t1 = fmaf(cz, b.z, t1);
        float t2 = fmaf(cx, c.x, c.w); t2 = fmaf(cy, c.y, t2); t2 = fmaf(cz, c.z, t2);
        float t3 = fmaf(cx, d.x, d.w); t3 = fmaf(cy, d.y, t3); t3 = fmaf(cz, d.z, t3);
        m = fminf(m, fminf(fminf(t0, t1), fminf(t2, t3)));
    }
    for (; j < n; j++) {
        const float4 a = t[j];
        float t0 = fmaf(cx, a.x, a.w); t0 = fmaf(cy, a.y, t0); t0 = fmaf(cz, a.z, t0);
        m = fminf(m, t0);
    }
}

__device__ __forceinline__ float block_reduce_sum256(float v, float* buf) {
    const int lane = threadIdx.x & 31, w = threadIdx.x >> 5;
#pragma unroll
    for (int o = 16; o > 0; o >>= 1) v += __shfl_down_sync(0xffffffffu, v, o);
    if (lane == 0) buf[w] = v;
    __syncthreads();
    if (w == 0) {
        v = (lane < 8) ? buf[lane] : 0.0f;
#pragma unroll
        for (int o = 4; o > 0; o >>= 1) v += __shfl_down_sync(0xffffffffu, v, o);
    }
    return v;
}

// decode group -> pointers/counts (shared by bound & scan kernels)
struct GInfo {
    const float4* qp;       // query slab base
    const float4* cp;       // counterpart cloud base
    const unsigned* ccnt;   // counterpart slab counts
    int qslab, qoff, qcnt, CCAP;
};
__device__ __forceinline__ GInfo group_info(int gid) {
    GInfo g;
    if (gid < NG1) {              // queries = shape slab, counterpart = skel
        const int b   = gid >> 8;            // /(NSLAB*SUB1)=256
        const int rem = gid & 255;
        g.qslab = rem >> 2;
        const int sub = rem & 3;
        g.qoff = sub * QG;
        const int tot = min((int)g_cntSh[b][g.qslab], SHCAP);
        g.qcnt = min(max(tot - g.qoff, 0), QG);
        g.qp = g_shp[b] + g.qslab * SHCAP;
        g.cp = g_skp[b]; g.ccnt = g_cntSk[b]; g.CCAP = SKCAP;
    } else {                      // queries = skel slab, counterpart = shape
        const int t = gid - NG1;
        const int b = t >> 6;                // /NSLAB
        g.qslab = t & 63;
        g.qoff = 0;
        g.qcnt = min((int)g_cntSk[b][g.qslab], SKCAP);
        g.qp = g_skp[b] + g.qslab * SKCAP;
        g.cp = g_shp[b]; g.ccnt = g_cntSh[b]; g.CCAP = SHCAP;
    }
    return g;
}

// ---------------------------------------------------------------------------
// Prep: bucket every point into its x-slab (atomic slot). ~1 us.
// ---------------------------------------------------------------------------
__global__ void __launch_bounds__(256) prep_kernel(
    const float* __restrict__ shape, const float* __restrict__ skel)
{
    const int i = blockIdx.x * 256 + threadIdx.x;
    if (i < BATCH * NSHAPE) {
        const int b = i >> 13;
        const float* p = shape + (size_t)i * 6;
        const float x = p[0], y = p[1], z = p[2];
        const int s = xbin(x);
        const unsigned slot = atomicAdd(&g_cntSh[b][s], 1u);
        if (slot < SHCAP)
            g_shp[b][s * SHCAP + slot] =
                make_float4(x, y, z, fmaf(x, x, fmaf(y, y, z * z)));
    } else {
        const int j = i - BATCH * NSHAPE;
        if (j < BATCH * NSKEL) {
            const int b = j >> 11;
            const float* p = skel + (size_t)j * 3;
            const float x = p[0], y = p[1], z = p[2];
            const int s = xbin(x);
            const unsigned slot = atomicAdd(&g_cntSk[b][s], 1u);
            if (slot < SKCAP)
                g_skp[b][s * SKCAP + slot] =
                    make_float4(x, y, z, fmaf(x, x, fmaf(y, y, z * z)));
        }
    }
}

// ---------------------------------------------------------------------------
// Bound: one block per group. Ring-gather >=64 counterpart points around the
// query slab into smem; dense scan -> per-query upper bound (seeds keys);
// block-max radius + block x-extent -> exact slab window header.
// ---------------------------------------------------------------------------
__global__ void __launch_bounds__(256) bound_kernel()
{
    __shared__ float4 cand[QG];
    __shared__ float rbuf[8], lobuf[8], hibuf[8];

    const int tid  = threadIdx.x;
    const int lane = tid & 31;
    const int w    = tid >> 5;
    const int gid  = blockIdx.x;
    const GInfo g  = group_info(gid);

    // ---- ring fill (nb is uniform: all threads compute identical values) ----
    int nb = 0;
    for (int r = 0; r < NSLAB && nb < 64; r++) {
        const int sa = g.qslab - r, sb = g.qslab + r;
        if (sa >= 0) {
            const int c = min((int)g.ccnt[sa], g.CCAP);
            const int take = min(c, QG - nb);
            for (int i = tid; i < take; i += 256) cand[nb + i] = g.cp[sa * g.CCAP + i];
            nb += take;
        }
        if (r > 0 && sb < NSLAB && nb < QG) {
            const int c = min((int)g.ccnt[sb], g.CCAP);
            const int take = min(c, QG - nb);
            for (int i = tid; i < take; i += 256) cand[nb + i] = g.cp[sb * g.CCAP + i];
            nb += take;
        }
    }
    __syncthreads();

    const bool act = tid < g.qcnt;
    const float4 q = act ? g.qp[g.qoff + tid] : make_float4(0.f, 0.f, 0.f, 0.f);
    const float cx = -2.0f * q.x, cy = -2.0f * q.y, cz = -2.0f * q.z;

    float m = CUDART_INF_F;
    scan_pts(cand, nb, cx, cy, cz, m);

    const float d2 = act ? fmaxf(q.w + m, 0.0f) : 0.0f;
    if (act) g_key[gid * QG + tid] = 0xFFFFFFFFu ^ __float_as_uint(d2);

    // block reduces: max radius, min/max qx over active lanes
    float rv = act ? sqrtf(d2) * 1.0001f : 0.0f;
    float lo = act ? q.x :  CUDART_INF_F;
    float hi = act ? q.x : -CUDART_INF_F;
#pragma unroll
    for (int o = 16; o > 0; o >>= 1) {
        rv = fmaxf(rv, __shfl_xor_sync(0xffffffffu, rv, o));
        lo = fminf(lo, __shfl_xor_sync(0xffffffffu, lo, o));
        hi = fmaxf(hi, __shfl_xor_sync(0xffffffffu, hi, o));
    }
    if (lane == 0) { rbuf[w] = rv; lobuf[w] = lo; hibuf[w] = hi; }
    __syncthreads();
    if (tid == 0) {
        float rm = 0.0f, xl = CUDART_INF_F, xh = -CUDART_INF_F;
#pragma unroll
        for (int i = 0; i < 8; i++) {
            rm = fmaxf(rm, rbuf[i]);
            xl = fminf(xl, lobuf[i]);
            xh = fmaxf(xh, hibuf[i]);
        }
        if (g.qcnt > 0) { g_s0[gid] = xbin(xl - rm); g_s1[gid] = xbin(xh + rm); }
        else            { g_s0[gid] = 0;             g_s1[gid] = -1; }
    }
}

// ---------------------------------------------------------------------------
// Scan: block = (group, chunk). Dense smem-tile scan of the group's window
// slabs (chunk-strided). Merge minima via atomicMax keys; last chunk
// finalizes; last group writes out[0] and resets slab counters.
// ---------------------------------------------------------------------------
__global__ void __launch_bounds__(256) scan_kernel(float* __restrict__ out)
{
    __shared__ float4 tile[QG];
    __shared__ unsigned sLastChunk;
    __shared__ unsigned sLastGroup;
    __shared__ float sbuf[8];

    const int tid = threadIdx.x;
    const int gid = blockIdx.x % NG;
    const int ch  = blockIdx.x / NG;
    const GInfo g = group_info(gid);

    const int s0 = g_s0[gid], s1 = g_s1[gid];

    const bool act = tid < g.qcnt;
    const float4 q = act ? g.qp[g.qoff + tid] : make_float4(0.f, 0.f, 0.f, 0.f);
    const float cx = -2.0f * q.x, cy = -2.0f * q.y, cz = -2.0f * q.z;
    float m = CUDART_INF_F;

    for (int s = s0 + ch; s <= s1; s += MAXCH) {
        const int c = min((int)g.ccnt[s], g.CCAP);
        for (int base = 0; base < c; base += QG) {
            const int n = min(QG, c - base);
            __syncthreads();
            if (tid < n) tile[tid] = g.cp[s * g.CCAP + base + tid];
            __syncthreads();
            scan_pts(tile, n, cx, cy, cz, m);
        }
    }

    if (act) {
        const float d2 = fmaxf(q.w + m, 0.0f);
        atomicMax(&g_key[gid * QG + tid], 0xFFFFFFFFu ^ __float_as_uint(d2));
    }

    // ---- group completion (all MAXCH chunk blocks participate) ----
    __threadfence();
    __syncthreads();
    if (tid == 0) sLastChunk = (atomicAdd(&g_gc[gid], 1u) == MAXCH - 1) ? 1u : 0u;
    __syncthreads();
    if (!sLastChunk) return;
    __threadfence();

    float s = 0.0f;
    if (act) {
        const unsigned k = atomicExch(&g_key[gid * QG + tid], 0u);
        s = sqrtf(__uint_as_float(0xFFFFFFFFu ^ k));
    }
    s = block_reduce_sum256(s, sbuf);

    if (tid == 0) {
        g_gc[gid] = 0;
        atomicAdd(&g_accum, s);
        __threadfence();
        sLastGroup = (atomicAdd(&g_done, 1u) == NG - 1) ? 1u : 0u;
    }
    __syncthreads();
    if (sLastGroup) {
        unsigned* c1 = &g_cntSh[0][0];
        unsigned* c2 = &g_cntSk[0][0];
        for (int i = tid; i < BATCH * NSLAB; i += 256) { c1[i] = 0; c2[i] = 0; }
        if (tid == 0) {
            out[0] = atomicExch(&g_accum, 0.0f) * 1.0e-4f;
            g_done = 0;
        }
    }
}

// ---------------------------------------------------------------------------
extern "C" void kernel_launch(void* const* d_in, const int* in_sizes, int n_in,
                              void* d_out, int out_size)
{
    const float* shape = (const float*)d_in[0];  // (8, 8192, 6) fp32
    const float* skel  = (const float*)d_in[1];  // (8, 2048, 3) fp32
    prep_kernel<<<(BATCH * (NSHAPE + NSKEL) + 255) / 256, 256>>>(shape, skel);
    bound_kernel<<<NG, 256>>>();
    scan_kernel<<<SCANBLK, 256>>>((float*)d_out);
}

// round 17
// speedup vs baseline: 4.7994x; 1.8145x over previous
#include <cuda_runtime.h>
#include <math_constants.h>

#define BATCH   8
#define NSHAPE  8192
#define NSKEL   2048

#define NSLAB   64
#define XMIN    (-6.0f)
#define INVW    5.3333333f             /* 64 slabs over [-6,6], width 0.1875 */

#define SHCAP   1024                   /* bucket capacity (peak ~640) */
#define SKCAP   256                    /* bucket capacity (peak ~165) */

#define QG      128                    /* queries per group */
#define NG1     (BATCH * NSHAPE / QG)  /* 512 */
#define NG2     (BATCH * NSKEL  / QG)  /* 128 */
#define NG      (NG1 + NG2)            /* 640 */
#define MAXCH   4
#define SCANBLK (NG * MAXCH)           /* 2560 */

// Buckets (stage 1) -> compact slab-ordered arrays + CDF (stage 2).
// Key = ~bits(d2): monotone-decreasing, so atomicMax == min(d2).
// All state rewritten each call or self-resetting => graph-replay safe.
__device__ float4   g_shp[BATCH][NSLAB * SHCAP];
__device__ float4   g_skp[BATCH][NSLAB * SKCAP];
__device__ unsigned g_cntSh[BATCH][NSLAB];
__device__ unsigned g_cntSk[BATCH][NSLAB];
__device__ float4   g_cSh[BATCH][NSHAPE];      // compact shape (slab-ordered)
__device__ float4   g_cSk[BATCH][NSKEL];       // compact skel
__device__ unsigned g_cdfSh[BATCH][NSLAB + 1];
__device__ unsigned g_cdfSk[BATCH][NSLAB + 1];
__device__ int      g_e0[NG], g_e1[NG];        // per-group entry window
__device__ unsigned g_key[NG * QG];            // seeded by bound each call
__device__ unsigned g_gc[NG];
__device__ unsigned g_done;
__device__ float    g_accum;

// ---------------------------------------------------------------------------
__device__ __forceinline__ int xbin(float x) {
    int s = (int)floorf((x - XMIN) * INVW);
    return min(max(s, 0), NSLAB - 1);
}

// dense scan of n smem points; m = min over (|p|^2 - 2 q.p)
__device__ __forceinline__ void scan_pts(
    const float4* __restrict__ t, int n,
    float cx, float cy, float cz, float& m)
{
    int j = 0;
    for (; j + 4 <= n; j += 4) {
        const float4 a = t[j + 0];
        const float4 b = t[j + 1];
        const float4 c = t[j + 2];
        const float4 d = t[j + 3];
        float t0 = fmaf(cx, a.x, a.w); t0 = fmaf(cy, a.y, t0); t0 = fmaf(cz, a.z, t0);
        float t1 = fmaf(cx, b.x, b.w); t1 = fmaf(cy, b.y, t1); t1 = fmaf(cz, b.z, t1);
        float t2 = fmaf(cx, c.x, c.w); t2 = fmaf(cy, c.y, t2); t2 = fmaf(cz, c.z, t2);
        float t3 = fmaf(cx, d.x, d.w); t3 = fmaf(cy, d.y, t3); t3 = fmaf(cz, d.z, t3);
        m = fminf(m, fminf(fminf(t0, t1), fminf(t2, t3)));
    }
    for (; j < n; j++) {
        const float4 a = t[j];
        float t0 = fmaf(cx, a.x, a.w); t0 = fmaf(cy, a.y, t0); t0 = fmaf(cz, a.z, t0);
        m = fminf(m, t0);
    }
}

__device__ __forceinline__ float block_reduce_sum128(float v, float* buf) {
    const int lane = threadIdx.x & 31, w = threadIdx.x >> 5;
#pragma unroll
    for (int o = 16; o > 0; o >>= 1) v += __shfl_down_sync(0xffffffffu, v, o);
    if (lane == 0) buf[w] = v;
    __syncthreads();
    if (w == 0) {
        v = (lane < 4) ? buf[lane] : 0.0f;
#pragma unroll
        for (int o = 2; o > 0; o >>= 1) v += __shfl_down_sync(0xffffffffu, v, o);
    }
    return v;
}

// ---------------------------------------------------------------------------
// Stage 1: bucket every point into its x-slab (atomic slot).
// ---------------------------------------------------------------------------
__global__ void __launch_bounds__(128) prep_kernel(
    const float* __restrict__ shape, const float* __restrict__ skel)
{
    const int i = blockIdx.x * 128 + threadIdx.x;
    if (i < BATCH * NSHAPE) {
        const int b = i >> 13;
        const float* p = shape + (size_t)i * 6;
        const float x = p[0], y = p[1], z = p[2];
        const int s = xbin(x);
        const unsigned slot = atomicAdd(&g_cntSh[b][s], 1u);
        if (slot < SHCAP)
            g_shp[b][s * SHCAP + slot] =
                make_float4(x, y, z, fmaf(x, x, fmaf(y, y, z * z)));
    } else {
        const int j = i - BATCH * NSHAPE;
        if (j < BATCH * NSKEL) {
            const int b = j >> 11;
            const float* p = skel + (size_t)j * 3;
            const float x = p[0], y = p[1], z = p[2];
            const int s = xbin(x);
            const unsigned slot = atomicAdd(&g_cntSk[b][s], 1u);
            if (slot < SKCAP)
                g_skp[b][s * SKCAP + slot] =
                    make_float4(x, y, z, fmaf(x, x, fmaf(y, y, z * z)));
        }
    }
}

// ---------------------------------------------------------------------------
// Stage 2: compaction. One block per (array, batch, slab): base = prefix of
// counts, copy bucket slab -> compact array, emit CDF entry.
// ---------------------------------------------------------------------------
__global__ void __launch_bounds__(128) compact_kernel()
{
    __shared__ unsigned spre[NSLAB];
    __shared__ unsigned sbase;

    const int tid = threadIdx.x;
    const int bid = blockIdx.x;                 // 0..1023
    const bool isShape = (bid < BATCH * NSLAB);
    const int  r    = isShape ? bid : bid - BATCH * NSLAB;
    const int  b    = r >> 6;
    const int  slab = r & 63;
    const int  CAP  = isShape ? SHCAP : SKCAP;
    const unsigned* cnt = isShape ? g_cntSh[b] : g_cntSk[b];

    if (tid < NSLAB) spre[tid] = min(cnt[tid], (unsigned)CAP);
    __syncthreads();
    if (tid == 0) {
        unsigned s = 0;
        for (int i = 0; i < slab; i++) s += spre[i];
        sbase = s;
    }
    __syncthreads();
    const unsigned base = sbase;
    const unsigned n    = spre[slab];

    const float4* src = (isShape ? g_shp[b] : g_skp[b]) + slab * CAP;
    float4*       dst = (isShape ? g_cSh[b] : g_cSk[b]);
    for (unsigned i = tid; i < n; i += 128) dst[base + i] = src[i];

    unsigned* cdf = isShape ? g_cdfSh[b] : g_cdfSk[b];
    if (tid == 0) {
        cdf[slab] = base;
        if (slab == NSLAB - 1) cdf[NSLAB] = base + n;
    }
}

// ---------------------------------------------------------------------------
// Stage 3: bound. One block per 128-query group (queries dense & x-coherent).
// Phase A: 256-pt rank window via CDF -> exact upper bound (seeds keys).
// Block-max radius + x-extent -> exact entry window [e0,e1).
// ---------------------------------------------------------------------------
__global__ void __launch_bounds__(128) bound_kernel()
{
    __shared__ float4 tile[QG];
    __shared__ float rbuf[4], lobuf[4], hibuf[4];

    const int tid = threadIdx.x;
    const int gid = blockIdx.x;

    const float4 *qp, *cp;
    const unsigned* cdf;
    int NE, qbase;
    if (gid < NG1) {                  // queries = shape, candidates = skel
        const int b = gid >> 6;
        qbase = (gid & 63) * QG;
        qp = g_cSh[b]; cp = g_cSk[b]; cdf = g_cdfSk[b]; NE = NSKEL;
    } else {                          // queries = skel, candidates = shape
        const int t = gid - NG1;
        const int b = t >> 4;
        qbase = (t & 15) * QG;
        qp = g_cSk[b]; cp = g_cSh[b]; cdf = g_cdfSh[b]; NE = NSHAPE;
    }

    const float4 q = qp[qbase + tid];
    const float cx = -2.0f * q.x, cy = -2.0f * q.y, cz = -2.0f * q.z;

    // block x extent (warp+block reduce)
    float lo = q.x, hi = q.x;
#pragma unroll
    for (int o = 16; o > 0; o >>= 1) {
        lo = fminf(lo, __shfl_xor_sync(0xffffffffu, lo, o));
        hi = fmaxf(hi, __shfl_xor_sync(0xffffffffu, hi, o));
    }
    if ((tid & 31) == 0) { lobuf[tid >> 5] = lo; hibuf[tid >> 5] = hi; }
    __syncthreads();
    const float xl = fminf(fminf(lobuf[0], lobuf[1]), fminf(lobuf[2], lobuf[3]));
    const float xh = fmaxf(fmaxf(hibuf[0], hibuf[1]), fmaxf(hibuf[2], hibuf[3]));

    // phase A: 256 candidate points centered at the group's x-mid rank
    const int c  = (int)cdf[xbin(0.5f * (xl + xh))];
    const int a0 = min(max(c - QG, 0), NE - 2 * QG);

    float m = CUDART_INF_F;
    for (int t = 0; t < 2; t++) {
        __syncthreads();
        tile[tid] = cp[a0 + t * QG + tid];
        __syncthreads();
        scan_pts(tile, QG, cx, cy, cz, m);
    }

    const float d2 = fmaxf(q.w + m, 0.0f);
    g_key[gid * QG + tid] = 0xFFFFFFFFu ^ __float_as_uint(d2);

    // block-max radius
    float rv = sqrtf(d2) * 1.0001f;
#pragma unroll
    for (int o = 16; o > 0; o >>= 1) rv = fmaxf(rv, __shfl_xor_sync(0xffffffffu, rv, o));
    if ((tid & 31) == 0) rbuf[tid >> 5] = rv;
    __syncthreads();
    if (tid == 0) {
        const float rm = fmaxf(fmaxf(rbuf[0], rbuf[1]), fmaxf(rbuf[2], rbuf[3]));
        g_e0[gid] = (int)cdf[xbin(xl - rm)];
        g_e1[gid] = (int)cdf[xbin(xh + rm) + 1];
    }
}

// ---------------------------------------------------------------------------
// Stage 4: scan. Block = (group, chunk): chunk-strided 128-entry smem tiles
// of the group's exact window; merge minima via atomicMax keys; last chunk
// finalizes the group; last group writes out[0] and resets counters.
// ---------------------------------------------------------------------------
__global__ void __launch_bounds__(128) scan_kernel(float* __restrict__ out)
{
    __shared__ float4 tile[QG];
    __shared__ unsigned sLastChunk, sLastGroup;
    __shared__ float sbuf[4];

    const int tid = threadIdx.x;
    const int gid = blockIdx.x % NG;
    const int ch  = blockIdx.x / NG;

    const float4 *qp, *cp;
    int qbase;
    if (gid < NG1) {
        const int b = gid >> 6;
        qbase = (gid & 63) * QG;
        qp = g_cSh[b]; cp = g_cSk[b];
    } else {
        const int t = gid - NG1;
        const int b = t >> 4;
        qbase = (t & 15) * QG;
        qp = g_cSk[b]; cp = g_cSh[b];
    }

    const int e0 = g_e0[gid], e1 = g_e1[gid];

    const float4 q = qp[qbase + tid];
    const float cx = -2.0f * q.x, cy = -2.0f * q.y, cz = -2.0f * q.z;
    float m = CUDART_INF_F;

    for (int t = e0 + ch * QG; t < e1; t += MAXCH * QG) {
        const int n = min(QG, e1 - t);
        __syncthreads();
        if (tid < n) tile[tid] = cp[t + tid];
        __syncthreads();
        scan_pts(tile, n, cx, cy, cz, m);
    }

    const float d2 = fmaxf(q.w + m, 0.0f);
    atomicMax(&g_key[gid * QG + tid], 0xFFFFFFFFu ^ __float_as_uint(d2));

    // ---- group completion ----
    __threadfence();
    __syncthreads();
    if (tid == 0) sLastChunk = (atomicAdd(&g_gc[gid], 1u) == MAXCH - 1) ? 1u : 0u;
    __syncthreads();
    if (!sLastChunk) return;
    __threadfence();

    const unsigned k = atomicExch(&g_key[gid * QG + tid], 0u);
    float s = sqrtf(__uint_as_float(0xFFFFFFFFu ^ k));
    s = block_reduce_sum128(s, sbuf);

    if (tid == 0) {
        g_gc[gid] = 0;
        atomicAdd(&g_accum, s);
        __threadfence();
        sLastGroup = (atomicAdd(&g_done, 1u) == NG - 1) ? 1u : 0u;
    }
    __syncthreads();
    if (sLastGroup) {
        unsigned* c1 = &g_cntSh[0][0];
        unsigned* c2 = &g_cntSk[0][0];
        for (int i = tid; i < BATCH * NSLAB; i += 128) { c1[i] = 0; c2[i] = 0; }
        if (tid == 0) {
            out[0] = atomicExch(&g_accum, 0.0f) * 1.0e-4f;
            g_done = 0;
        }
    }
}

// ---------------------------------------------------------------------------
extern "C" void kernel_launch(void* const* d_in, const int* in_sizes, int n_in,
                              void* d_out, int out_size)
{
    const float* shape = (const float*)d_in[0];  // (8, 8192, 6) fp32
    const float* skel  = (const float*)d_in[1];  // (8, 2048, 3) fp32
    prep_kernel<<<(BATCH * (NSHAPE + NSKEL) + 127) / 128, 128>>>(shape, skel);
    compact_kernel<<<2 * BATCH * NSLAB, 128>>>();
    bound_kernel<<<NG, 128>>>();
    scan_kernel<<<SCANBLK, 128>>>((float*)d_out);
}